// round 15
// baseline (speedup 1.0000x reference)
#include <cuda_runtime.h>

// ---------------------------------------------------------------------------
// Problem constants (fixed by the reference)
// ---------------------------------------------------------------------------
#define T_TOT   2048            // tokens per batch
#define TA      1024            // tokens per stream per batch
#define E       2048            // embed dim (E_A == E_B == E_ATT)
#define C3      6144            // 3 * E_ATT
#define NH      16
#define HSZ     128
#define NTOK    4096            // B * T

// Scratch (allocation-free rule: device globals)
__device__ float g_qkv[(size_t)NTOK * C3];   // (B*T, 3*E) interleaved qkv
__device__ float g_y  [(size_t)NTOK * E];    // (B*T, E) attention output

// token row map: stream-local row r (b*1024 + ta)  ->  global token (b*2048 + 2*ta + parity)
__device__ __forceinline__ int map_row(int r, int parity) {
    return ((r >> 10) << 11) | ((r & 1023) << 1) | parity;
}

// ---------------------------------------------------------------------------
// SGEMM: C[M,N] = A[M,K] @ B[K,N], 128x128x16 tiles, 256 thr, 8x8 microtile.
// mapA: gather A rows from g_y via map_row. mapC: scatter C rows into g_qkv.
// M = gridDim.y*128, N = gridDim.x*128 (all dims multiples of tile sizes).
// ---------------------------------------------------------------------------
__global__ __launch_bounds__(256, 2)
void sgemm_map_kernel(const float* __restrict__ A, const float* __restrict__ Bm,
                      float* __restrict__ C, int K, int lda, int ldb, int ldc,
                      int parity, int mapA, int mapC)
{
    __shared__ float As[16][132];   // transposed A tile, padded (2-way max on store)
    __shared__ float Bs[16][128];

    const float* Abase = mapA ? g_y   : A;
    float*       Cbase = mapC ? g_qkv : C;

    const int tid = threadIdx.x;
    const int m0 = blockIdx.y << 7;
    const int n0 = blockIdx.x << 7;
    const int tx = tid & 15;
    const int ty = tid >> 4;

    float acc[8][8];
#pragma unroll
    for (int i = 0; i < 8; ++i)
#pragma unroll
        for (int j = 0; j < 8; ++j) acc[i][j] = 0.f;

    const int a_r = tid >> 2;            // 0..63
    const int a_c = (tid & 3) << 2;      // 0,4,8,12
    const int b_r = tid >> 5;            // 0..7
    const int b_c = (tid & 31) << 2;     // 0..124

    int ar0 = m0 + a_r, ar1 = m0 + a_r + 64;
    if (mapA) { ar0 = map_row(ar0, parity); ar1 = map_row(ar1, parity); }
    const float* Ap0 = Abase + (size_t)ar0 * lda + a_c;
    const float* Ap1 = Abase + (size_t)ar1 * lda + a_c;
    const float* Bp  = Bm + (size_t)b_r * ldb + n0 + b_c;

    for (int kt = 0; kt < K; kt += 16) {
        float4 av0 = *(const float4*)(Ap0 + kt);
        float4 av1 = *(const float4*)(Ap1 + kt);
        float4 bv0 = *(const float4*)(Bp + (size_t)kt * ldb);
        float4 bv1 = *(const float4*)(Bp + (size_t)(kt + 8) * ldb);
        As[a_c + 0][a_r]      = av0.x; As[a_c + 1][a_r]      = av0.y;
        As[a_c + 2][a_r]      = av0.z; As[a_c + 3][a_r]      = av0.w;
        As[a_c + 0][a_r + 64] = av1.x; As[a_c + 1][a_r + 64] = av1.y;
        As[a_c + 2][a_r + 64] = av1.z; As[a_c + 3][a_r + 64] = av1.w;
        *(float4*)&Bs[b_r][b_c]     = bv0;
        *(float4*)&Bs[b_r + 8][b_c] = bv1;
        __syncthreads();
#pragma unroll
        for (int k = 0; k < 16; ++k) {
            float4 a0 = *(const float4*)&As[k][ty << 3];
            float4 a1 = *(const float4*)&As[k][(ty << 3) + 4];
            float4 b0 = *(const float4*)&Bs[k][tx << 3];
            float4 b1 = *(const float4*)&Bs[k][(tx << 3) + 4];
            float af[8] = {a0.x, a0.y, a0.z, a0.w, a1.x, a1.y, a1.z, a1.w};
            float bf[8] = {b0.x, b0.y, b0.z, b0.w, b1.x, b1.y, b1.z, b1.w};
#pragma unroll
            for (int i = 0; i < 8; ++i)
#pragma unroll
                for (int j = 0; j < 8; ++j)
                    acc[i][j] += af[i] * bf[j];
        }
        __syncthreads();
    }

#pragma unroll
    for (int i = 0; i < 8; ++i) {
        int gr = m0 + (ty << 3) + i;
        if (mapC) gr = map_row(gr, parity);
        float* cp = Cbase + (size_t)gr * ldc + n0 + (tx << 3);
        float4 v0 = make_float4(acc[i][0], acc[i][1], acc[i][2], acc[i][3]);
        float4 v1 = make_float4(acc[i][4], acc[i][5], acc[i][6], acc[i][7]);
        *(float4*)cp       = v0;
        *(float4*)(cp + 4) = v1;
    }
}

// ---------------------------------------------------------------------------
// RoPE in-place on Q and K sections of g_qkv.
// idx -> (tok, qk, h, d<64); rotate pair (d, d+64).
// ---------------------------------------------------------------------------
__global__ void rope_kernel(const float* __restrict__ cp, const float* __restrict__ sp)
{
    int idx = blockIdx.x * blockDim.x + threadIdx.x;   // 0 .. 8388607
    int d   = idx & 63;
    int h   = (idx >> 6) & 15;
    int qk  = (idx >> 10) & 1;
    int tok = idx >> 11;                 // 0..4095
    int t   = tok & (T_TOT - 1);
    size_t base = (size_t)tok * C3 + (qk << 11) + (h << 7);
    float x1 = g_qkv[base + d];
    float x2 = g_qkv[base + d + 64];
    float c1 = cp[(t << 7) + d],      s1 = sp[(t << 7) + d];
    float c2 = cp[(t << 7) + d + 64], s2 = sp[(t << 7) + d + 64];
    g_qkv[base + d]      = x1 * c1 - x2 * s1;   // x*cos + (-x2)*sin
    g_qkv[base + d + 64] = x2 * c2 + x1 * s2;   // x*cos + ( x1)*sin
}

// ---------------------------------------------------------------------------
// Causal flash attention, fp32. BQ = BK = 64, D = 128, 256 threads.
// Thread (rm = tid>>4, cn = tid&15): S rows 4rm..4rm+3, S cols 4cn..4cn+3,
// O cols 8cn..8cn+7. Row softmax stats reduced over 16-lane groups (shfl).
// grid = (32 qtiles [reversed], 32 b*h).
// ---------------------------------------------------------------------------
#define FLASH_SMEM ((128 * 65 * 2 + 64 * 128 + 64 * 65) * 4)

__global__ __launch_bounds__(256, 1)
void flash_kernel()
{
    extern __shared__ float sm[];
    float* sQ = sm;                       // [128][65]  k-major (transposed)
    float* sK = sm + 128 * 65;            // [128][65]  k-major (transposed)
    float* sV = sK + 128 * 65;            // [64][128]  natural
    float* sP = sV + 64 * 128;            // [64][65]

    const int tid   = threadIdx.x;
    const int qtile = 31 - blockIdx.x;    // heavy (late) q-tiles scheduled first
    const int bh    = blockIdx.y;
    const int b     = bh >> 4;
    const int h     = bh & 15;
    const int qt0   = qtile << 6;
    const int rm    = tid >> 4;
    const int cn    = tid & 15;

    const float* base = g_qkv + (size_t)b * T_TOT * C3 + (h << 7);

    // Load Q tile, transposed into sQ[k][r]
    for (int idx = tid; idx < 2048; idx += 256) {
        int r = idx >> 5, d4 = (idx & 31) << 2;
        float4 v = *(const float4*)(base + (size_t)(qt0 + r) * C3 + d4);
        sQ[(d4 + 0) * 65 + r] = v.x;
        sQ[(d4 + 1) * 65 + r] = v.y;
        sQ[(d4 + 2) * 65 + r] = v.z;
        sQ[(d4 + 3) * 65 + r] = v.w;
    }

    float o[4][8];
#pragma unroll
    for (int i = 0; i < 4; ++i)
#pragma unroll
        for (int j = 0; j < 8; ++j) o[i][j] = 0.f;
    float mrow[4] = {-1e30f, -1e30f, -1e30f, -1e30f};
    float lrow[4] = {0.f, 0.f, 0.f, 0.f};
    const float scale = 0.08838834764831845f;   // 1/sqrt(128)

    for (int kt = 0; kt <= qtile; ++kt) {
        const int kt0 = kt << 6;
        __syncthreads();   // previous iteration done with sK/sV/sP
        // Load K (transposed) and V (natural) tiles
        for (int idx = tid; idx < 2048; idx += 256) {
            int r = idx >> 5, d4 = (idx & 31) << 2;
            const float* rp = base + (size_t)(kt0 + r) * C3 + d4;
            float4 kv = *(const float4*)(rp + 2048);
            sK[(d4 + 0) * 65 + r] = kv.x;
            sK[(d4 + 1) * 65 + r] = kv.y;
            sK[(d4 + 2) * 65 + r] = kv.z;
            sK[(d4 + 3) * 65 + r] = kv.w;
            float4 vv = *(const float4*)(rp + 4096);
            *(float4*)&sV[(r << 7) + d4] = vv;
        }
        __syncthreads();

        // S = Q K^T (4x4 per thread)
        float acc[4][4];
#pragma unroll
        for (int i = 0; i < 4; ++i)
#pragma unroll
            for (int j = 0; j < 4; ++j) acc[i][j] = 0.f;

#pragma unroll 4
        for (int k = 0; k < 128; ++k) {
            const float* qr = sQ + k * 65 + (rm << 2);
            const float* kr = sK + k * 65 + (cn << 2);
            float a0 = qr[0], a1 = qr[1], a2 = qr[2], a3 = qr[3];
            float b0 = kr[0], b1 = kr[1], b2 = kr[2], b3 = kr[3];
            acc[0][0] += a0 * b0; acc[0][1] += a0 * b1; acc[0][2] += a0 * b2; acc[0][3] += a0 * b3;
            acc[1][0] += a1 * b0; acc[1][1] += a1 * b1; acc[1][2] += a1 * b2; acc[1][3] += a1 * b3;
            acc[2][0] += a2 * b0; acc[2][1] += a2 * b1; acc[2][2] += a2 * b2; acc[2][3] += a2 * b3;
            acc[3][0] += a3 * b0; acc[3][1] += a3 * b1; acc[3][2] += a3 * b2; acc[3][3] += a3 * b3;
        }

        const bool diag = (kt == qtile);
#pragma unroll
        for (int i = 0; i < 4; ++i) {
            float s0 = acc[i][0] * scale, s1 = acc[i][1] * scale;
            float s2 = acc[i][2] * scale, s3 = acc[i][3] * scale;
            if (diag) {
                int iq = (rm << 2) + i;
                int jc = cn << 2;
                if (jc + 0 > iq) s0 = -1e30f;
                if (jc + 1 > iq) s1 = -1e30f;
                if (jc + 2 > iq) s2 = -1e30f;
                if (jc + 3 > iq) s3 = -1e30f;
            }
            // 16-lane row-group reductions (lanes sharing rm are contiguous 16)
            float mx = fmaxf(fmaxf(s0, s1), fmaxf(s2, s3));
            mx = fmaxf(mx, __shfl_xor_sync(0xffffffffu, mx, 1));
            mx = fmaxf(mx, __shfl_xor_sync(0xffffffffu, mx, 2));
            mx = fmaxf(mx, __shfl_xor_sync(0xffffffffu, mx, 4));
            mx = fmaxf(mx, __shfl_xor_sync(0xffffffffu, mx, 8));
            float mnew = fmaxf(mrow[i], mx);
            float corr = __expf(mrow[i] - mnew);
            float p0 = __expf(s0 - mnew);
            float p1 = __expf(s1 - mnew);
            float p2 = __expf(s2 - mnew);
            float p3 = __expf(s3 - mnew);
            float ls = (p0 + p1) + (p2 + p3);
            ls += __shfl_xor_sync(0xffffffffu, ls, 1);
            ls += __shfl_xor_sync(0xffffffffu, ls, 2);
            ls += __shfl_xor_sync(0xffffffffu, ls, 4);
            ls += __shfl_xor_sync(0xffffffffu, ls, 8);
            lrow[i] = lrow[i] * corr + ls;
            mrow[i] = mnew;
#pragma unroll
            for (int j = 0; j < 8; ++j) o[i][j] *= corr;
            float* pr = sP + ((rm << 2) + i) * 65 + (cn << 2);
            pr[0] = p0; pr[1] = p1; pr[2] = p2; pr[3] = p3;
        }
        __syncthreads();   // sP visible to all

        // O += P V
#pragma unroll 2
        for (int j = 0; j < 64; ++j) {
            float p0 = sP[((rm << 2) + 0) * 65 + j];
            float p1 = sP[((rm << 2) + 1) * 65 + j];
            float p2 = sP[((rm << 2) + 2) * 65 + j];
            float p3 = sP[((rm << 2) + 3) * 65 + j];
            float4 v0 = *(const float4*)&sV[(j << 7) + (cn << 3)];
            float4 v1 = *(const float4*)&sV[(j << 7) + (cn << 3) + 4];
            o[0][0] += p0 * v0.x; o[0][1] += p0 * v0.y; o[0][2] += p0 * v0.z; o[0][3] += p0 * v0.w;
            o[0][4] += p0 * v1.x; o[0][5] += p0 * v1.y; o[0][6] += p0 * v1.z; o[0][7] += p0 * v1.w;
            o[1][0] += p1 * v0.x; o[1][1] += p1 * v0.y; o[1][2] += p1 * v0.z; o[1][3] += p1 * v0.w;
            o[1][4] += p1 * v1.x; o[1][5] += p1 * v1.y; o[1][6] += p1 * v1.z; o[1][7] += p1 * v1.w;
            o[2][0] += p2 * v0.x; o[2][1] += p2 * v0.y; o[2][2] += p2 * v0.z; o[2][3] += p2 * v0.w;
            o[2][4] += p2 * v1.x; o[2][5] += p2 * v1.y; o[2][6] += p2 * v1.z; o[2][7] += p2 * v1.w;
            o[3][0] += p3 * v0.x; o[3][1] += p3 * v0.y; o[3][2] += p3 * v0.z; o[3][3] += p3 * v0.w;
            o[3][4] += p3 * v1.x; o[3][5] += p3 * v1.y; o[3][6] += p3 * v1.z; o[3][7] += p3 * v1.w;
        }
    }

    // Normalize and store to g_y (B*T, E) at head slice
#pragma unroll
    for (int i = 0; i < 4; ++i) {
        float inv = 1.f / lrow[i];
        int t = qt0 + (rm << 2) + i;
        float* yp = g_y + ((size_t)b * T_TOT + t) * E + (h << 7) + (cn << 3);
        float4 w0 = make_float4(o[i][0] * inv, o[i][1] * inv, o[i][2] * inv, o[i][3] * inv);
        float4 w1 = make_float4(o[i][4] * inv, o[i][5] * inv, o[i][6] * inv, o[i][7] * inv);
        *(float4*)yp       = w0;
        *(float4*)(yp + 4) = w1;
    }
}

// ---------------------------------------------------------------------------
// kernel_launch: 6 kernel launches, graph-capturable, allocation-free.
// Input order (metadata): x_a, x_b, cos, sin, mask_a, Wqkv_a, Wqkv_b, Wproj_a, Wproj_b
// mask_a is deterministic (t even -> A) so it is not read.
// Output: y_a (2048x2048) followed by y_b (2048x2048), float32.
// ---------------------------------------------------------------------------
extern "C" void kernel_launch(void* const* d_in, const int* in_sizes, int n_in,
                              void* d_out, int out_size)
{
    (void)in_sizes; (void)n_in; (void)out_size;
    const float* x_a     = (const float*)d_in[0];
    const float* x_b     = (const float*)d_in[1];
    const float* cosp    = (const float*)d_in[2];
    const float* sinp    = (const float*)d_in[3];
    const float* Wqkv_a  = (const float*)d_in[5];
    const float* Wqkv_b  = (const float*)d_in[6];
    const float* Wproj_a = (const float*)d_in[7];
    const float* Wproj_b = (const float*)d_in[8];
    float* out = (float*)d_out;

    cudaFuncSetAttribute(flash_kernel,
                         cudaFuncAttributeMaxDynamicSharedMemorySize, FLASH_SMEM);

    // QKV projections: (2048 x 6144) = x @ Wqkv, scattered rows into g_qkv
    sgemm_map_kernel<<<dim3(48, 16), 256>>>(x_a, Wqkv_a, nullptr,
                                            E, E, C3, C3, /*parity=*/0, /*mapA=*/0, /*mapC=*/1);
    sgemm_map_kernel<<<dim3(48, 16), 256>>>(x_b, Wqkv_b, nullptr,
                                            E, E, C3, C3, 1, 0, 1);

    // RoPE on Q and K in-place
    rope_kernel<<<32768, 256>>>(cosp, sinp);

    // Causal flash attention -> g_y
    flash_kernel<<<dim3(32, 32), 256, FLASH_SMEM>>>();

    // Output projections: gather even/odd token rows of g_y
    sgemm_map_kernel<<<dim3(16, 16), 256>>>(nullptr, Wproj_a, out,
                                            E, E, E, E, 0, /*mapA=*/1, /*mapC=*/0);
    sgemm_map_kernel<<<dim3(16, 16), 256>>>(nullptr, Wproj_b, out + (size_t)2048 * 2048,
                                            E, E, E, E, 1, 1, 0);
}

// round 16
// speedup vs baseline: 1.0001x; 1.0001x over previous
#include <cuda_runtime.h>

// ---------------------------------------------------------------------------
// Problem constants (fixed by the reference)
// ---------------------------------------------------------------------------
#define T_TOT   2048            // tokens per batch
#define TA      1024            // tokens per stream per batch
#define E       2048            // embed dim (E_A == E_B == E_ATT)
#define C3      6144            // 3 * E_ATT
#define NH      16
#define HSZ     128
#define NTOK    4096            // B * T

// Scratch (allocation-free rule: device globals)
__device__ float g_qkv[(size_t)NTOK * C3];   // (B*T, 3*E) interleaved qkv
__device__ float g_y  [(size_t)NTOK * E];    // (B*T, E) attention output

// token row map: stream-local row r (b*1024 + ta)  ->  global token (b*2048 + 2*ta + parity)
__device__ __forceinline__ int map_row(int r, int parity) {
    return ((r >> 10) << 11) | ((r & 1023) << 1) | parity;
}

// ---------------------------------------------------------------------------
// SGEMM: C[M,N] = A[M,K] @ B[K,N], 128x128x16 tiles, 256 thr, 8x8 microtile.
// mapA: gather A rows from g_y via map_row. mapC: scatter C rows into g_qkv.
// M = gridDim.y*128, N = gridDim.x*128 (all dims multiples of tile sizes).
// ---------------------------------------------------------------------------
__global__ __launch_bounds__(256, 2)
void sgemm_map_kernel(const float* __restrict__ A, const float* __restrict__ Bm,
                      float* __restrict__ C, int K, int lda, int ldb, int ldc,
                      int parity, int mapA, int mapC)
{
    __shared__ float As[16][132];   // transposed A tile, padded (2-way max on store)
    __shared__ float Bs[16][128];

    const float* Abase = mapA ? g_y   : A;
    float*       Cbase = mapC ? g_qkv : C;

    const int tid = threadIdx.x;
    const int m0 = blockIdx.y << 7;
    const int n0 = blockIdx.x << 7;
    const int tx = tid & 15;
    const int ty = tid >> 4;

    float acc[8][8];
#pragma unroll
    for (int i = 0; i < 8; ++i)
#pragma unroll
        for (int j = 0; j < 8; ++j) acc[i][j] = 0.f;

    const int a_r = tid >> 2;            // 0..63
    const int a_c = (tid & 3) << 2;      // 0,4,8,12
    const int b_r = tid >> 5;            // 0..7
    const int b_c = (tid & 31) << 2;     // 0..124

    int ar0 = m0 + a_r, ar1 = m0 + a_r + 64;
    if (mapA) { ar0 = map_row(ar0, parity); ar1 = map_row(ar1, parity); }
    const float* Ap0 = Abase + (size_t)ar0 * lda + a_c;
    const float* Ap1 = Abase + (size_t)ar1 * lda + a_c;
    const float* Bp  = Bm + (size_t)b_r * ldb + n0 + b_c;

    for (int kt = 0; kt < K; kt += 16) {
        float4 av0 = *(const float4*)(Ap0 + kt);
        float4 av1 = *(const float4*)(Ap1 + kt);
        float4 bv0 = *(const float4*)(Bp + (size_t)kt * ldb);
        float4 bv1 = *(const float4*)(Bp + (size_t)(kt + 8) * ldb);
        As[a_c + 0][a_r]      = av0.x; As[a_c + 1][a_r]      = av0.y;
        As[a_c + 2][a_r]      = av0.z; As[a_c + 3][a_r]      = av0.w;
        As[a_c + 0][a_r + 64] = av1.x; As[a_c + 1][a_r + 64] = av1.y;
        As[a_c + 2][a_r + 64] = av1.z; As[a_c + 3][a_r + 64] = av1.w;
        *(float4*)&Bs[b_r][b_c]     = bv0;
        *(float4*)&Bs[b_r + 8][b_c] = bv1;
        __syncthreads();
#pragma unroll
        for (int k = 0; k < 16; ++k) {
            float4 a0 = *(const float4*)&As[k][ty << 3];
            float4 a1 = *(const float4*)&As[k][(ty << 3) + 4];
            float4 b0 = *(const float4*)&Bs[k][tx << 3];
            float4 b1 = *(const float4*)&Bs[k][(tx << 3) + 4];
            float af[8] = {a0.x, a0.y, a0.z, a0.w, a1.x, a1.y, a1.z, a1.w};
            float bf[8] = {b0.x, b0.y, b0.z, b0.w, b1.x, b1.y, b1.z, b1.w};
#pragma unroll
            for (int i = 0; i < 8; ++i)
#pragma unroll
                for (int j = 0; j < 8; ++j)
                    acc[i][j] += af[i] * bf[j];
        }
        __syncthreads();
    }

#pragma unroll
    for (int i = 0; i < 8; ++i) {
        int gr = m0 + (ty << 3) + i;
        if (mapC) gr = map_row(gr, parity);
        float* cp = Cbase + (size_t)gr * ldc + n0 + (tx << 3);
        float4 v0 = make_float4(acc[i][0], acc[i][1], acc[i][2], acc[i][3]);
        float4 v1 = make_float4(acc[i][4], acc[i][5], acc[i][6], acc[i][7]);
        *(float4*)cp       = v0;
        *(float4*)(cp + 4) = v1;
    }
}

// ---------------------------------------------------------------------------
// RoPE in-place on Q and K sections of g_qkv.
// idx -> (tok, qk, h, d<64); rotate pair (d, d+64).
// ---------------------------------------------------------------------------
__global__ void rope_kernel(const float* __restrict__ cp, const float* __restrict__ sp)
{
    int idx = blockIdx.x * blockDim.x + threadIdx.x;   // 0 .. 8388607
    int d   = idx & 63;
    int h   = (idx >> 6) & 15;
    int qk  = (idx >> 10) & 1;
    int tok = idx >> 11;                 // 0..4095
    int t   = tok & (T_TOT - 1);
    size_t base = (size_t)tok * C3 + (qk << 11) + (h << 7);
    float x1 = g_qkv[base + d];
    float x2 = g_qkv[base + d + 64];
    float c1 = cp[(t << 7) + d],      s1 = sp[(t << 7) + d];
    float c2 = cp[(t << 7) + d + 64], s2 = sp[(t << 7) + d + 64];
    g_qkv[base + d]      = x1 * c1 - x2 * s1;   // x*cos + (-x2)*sin
    g_qkv[base + d + 64] = x2 * c2 + x1 * s2;   // x*cos + ( x1)*sin
}

// ---------------------------------------------------------------------------
// Causal flash attention, fp32. BQ = BK = 64, D = 128, 256 threads.
// Thread (rm = tid>>4, cn = tid&15): S rows 4rm..4rm+3, S cols 4cn..4cn+3,
// O cols 8cn..8cn+7. Row softmax stats reduced over 16-lane groups (shfl).
// grid = (32 qtiles [reversed], 32 b*h).
// ---------------------------------------------------------------------------
#define FLASH_SMEM ((128 * 65 * 2 + 64 * 128 + 64 * 65) * 4)

__global__ __launch_bounds__(256, 1)
void flash_kernel()
{
    extern __shared__ float sm[];
    float* sQ = sm;                       // [128][65]  k-major (transposed)
    float* sK = sm + 128 * 65;            // [128][65]  k-major (transposed)
    float* sV = sK + 128 * 65;            // [64][128]  natural
    float* sP = sV + 64 * 128;            // [64][65]

    const int tid   = threadIdx.x;
    const int qtile = 31 - blockIdx.x;    // heavy (late) q-tiles scheduled first
    const int bh    = blockIdx.y;
    const int b     = bh >> 4;
    const int h     = bh & 15;
    const int qt0   = qtile << 6;
    const int rm    = tid >> 4;
    const int cn    = tid & 15;

    const float* base = g_qkv + (size_t)b * T_TOT * C3 + (h << 7);

    // Load Q tile, transposed into sQ[k][r]
    for (int idx = tid; idx < 2048; idx += 256) {
        int r = idx >> 5, d4 = (idx & 31) << 2;
        float4 v = *(const float4*)(base + (size_t)(qt0 + r) * C3 + d4);
        sQ[(d4 + 0) * 65 + r] = v.x;
        sQ[(d4 + 1) * 65 + r] = v.y;
        sQ[(d4 + 2) * 65 + r] = v.z;
        sQ[(d4 + 3) * 65 + r] = v.w;
    }

    float o[4][8];
#pragma unroll
    for (int i = 0; i < 4; ++i)
#pragma unroll
        for (int j = 0; j < 8; ++j) o[i][j] = 0.f;
    float mrow[4] = {-1e30f, -1e30f, -1e30f, -1e30f};
    float lrow[4] = {0.f, 0.f, 0.f, 0.f};
    const float scale = 0.08838834764831845f;   // 1/sqrt(128)

    for (int kt = 0; kt <= qtile; ++kt) {
        const int kt0 = kt << 6;
        __syncthreads();   // previous iteration done with sK/sV/sP
        // Load K (transposed) and V (natural) tiles
        for (int idx = tid; idx < 2048; idx += 256) {
            int r = idx >> 5, d4 = (idx & 31) << 2;
            const float* rp = base + (size_t)(kt0 + r) * C3 + d4;
            float4 kv = *(const float4*)(rp + 2048);
            sK[(d4 + 0) * 65 + r] = kv.x;
            sK[(d4 + 1) * 65 + r] = kv.y;
            sK[(d4 + 2) * 65 + r] = kv.z;
            sK[(d4 + 3) * 65 + r] = kv.w;
            float4 vv = *(const float4*)(rp + 4096);
            *(float4*)&sV[(r << 7) + d4] = vv;
        }
        __syncthreads();

        // S = Q K^T (4x4 per thread)
        float acc[4][4];
#pragma unroll
        for (int i = 0; i < 4; ++i)
#pragma unroll
            for (int j = 0; j < 4; ++j) acc[i][j] = 0.f;

#pragma unroll 4
        for (int k = 0; k < 128; ++k) {
            const float* qr = sQ + k * 65 + (rm << 2);
            const float* kr = sK + k * 65 + (cn << 2);
            float a0 = qr[0], a1 = qr[1], a2 = qr[2], a3 = qr[3];
            float b0 = kr[0], b1 = kr[1], b2 = kr[2], b3 = kr[3];
            acc[0][0] += a0 * b0; acc[0][1] += a0 * b1; acc[0][2] += a0 * b2; acc[0][3] += a0 * b3;
            acc[1][0] += a1 * b0; acc[1][1] += a1 * b1; acc[1][2] += a1 * b2; acc[1][3] += a1 * b3;
            acc[2][0] += a2 * b0; acc[2][1] += a2 * b1; acc[2][2] += a2 * b2; acc[2][3] += a2 * b3;
            acc[3][0] += a3 * b0; acc[3][1] += a3 * b1; acc[3][2] += a3 * b2; acc[3][3] += a3 * b3;
        }

        const bool diag = (kt == qtile);
#pragma unroll
        for (int i = 0; i < 4; ++i) {
            float s0 = acc[i][0] * scale, s1 = acc[i][1] * scale;
            float s2 = acc[i][2] * scale, s3 = acc[i][3] * scale;
            if (diag) {
                int iq = (rm << 2) + i;
                int jc = cn << 2;
                if (jc + 0 > iq) s0 = -1e30f;
                if (jc + 1 > iq) s1 = -1e30f;
                if (jc + 2 > iq) s2 = -1e30f;
                if (jc + 3 > iq) s3 = -1e30f;
            }
            // 16-lane row-group reductions (lanes sharing rm are contiguous 16)
            float mx = fmaxf(fmaxf(s0, s1), fmaxf(s2, s3));
            mx = fmaxf(mx, __shfl_xor_sync(0xffffffffu, mx, 1));
            mx = fmaxf(mx, __shfl_xor_sync(0xffffffffu, mx, 2));
            mx = fmaxf(mx, __shfl_xor_sync(0xffffffffu, mx, 4));
            mx = fmaxf(mx, __shfl_xor_sync(0xffffffffu, mx, 8));
            float mnew = fmaxf(mrow[i], mx);
            float corr = __expf(mrow[i] - mnew);
            float p0 = __expf(s0 - mnew);
            float p1 = __expf(s1 - mnew);
            float p2 = __expf(s2 - mnew);
            float p3 = __expf(s3 - mnew);
            float ls = (p0 + p1) + (p2 + p3);
            ls += __shfl_xor_sync(0xffffffffu, ls, 1);
            ls += __shfl_xor_sync(0xffffffffu, ls, 2);
            ls += __shfl_xor_sync(0xffffffffu, ls, 4);
            ls += __shfl_xor_sync(0xffffffffu, ls, 8);
            lrow[i] = lrow[i] * corr + ls;
            mrow[i] = mnew;
#pragma unroll
            for (int j = 0; j < 8; ++j) o[i][j] *= corr;
            float* pr = sP + ((rm << 2) + i) * 65 + (cn << 2);
            pr[0] = p0; pr[1] = p1; pr[2] = p2; pr[3] = p3;
        }
        __syncthreads();   // sP visible to all

        // O += P V
#pragma unroll 2
        for (int j = 0; j < 64; ++j) {
            float p0 = sP[((rm << 2) + 0) * 65 + j];
            float p1 = sP[((rm << 2) + 1) * 65 + j];
            float p2 = sP[((rm << 2) + 2) * 65 + j];
            float p3 = sP[((rm << 2) + 3) * 65 + j];
            float4 v0 = *(const float4*)&sV[(j << 7) + (cn << 3)];
            float4 v1 = *(const float4*)&sV[(j << 7) + (cn << 3) + 4];
            o[0][0] += p0 * v0.x; o[0][1] += p0 * v0.y; o[0][2] += p0 * v0.z; o[0][3] += p0 * v0.w;
            o[0][4] += p0 * v1.x; o[0][5] += p0 * v1.y; o[0][6] += p0 * v1.z; o[0][7] += p0 * v1.w;
            o[1][0] += p1 * v0.x; o[1][1] += p1 * v0.y; o[1][2] += p1 * v0.z; o[1][3] += p1 * v0.w;
            o[1][4] += p1 * v1.x; o[1][5] += p1 * v1.y; o[1][6] += p1 * v1.z; o[1][7] += p1 * v1.w;
            o[2][0] += p2 * v0.x; o[2][1] += p2 * v0.y; o[2][2] += p2 * v0.z; o[2][3] += p2 * v0.w;
            o[2][4] += p2 * v1.x; o[2][5] += p2 * v1.y; o[2][6] += p2 * v1.z; o[2][7] += p2 * v1.w;
            o[3][0] += p3 * v0.x; o[3][1] += p3 * v0.y; o[3][2] += p3 * v0.z; o[3][3] += p3 * v0.w;
            o[3][4] += p3 * v1.x; o[3][5] += p3 * v1.y; o[3][6] += p3 * v1.z; o[3][7] += p3 * v1.w;
        }
    }

    // Normalize and store to g_y (B*T, E) at head slice
#pragma unroll
    for (int i = 0; i < 4; ++i) {
        float inv = 1.f / lrow[i];
        int t = qt0 + (rm << 2) + i;
        float* yp = g_y + ((size_t)b * T_TOT + t) * E + (h << 7) + (cn << 3);
        float4 w0 = make_float4(o[i][0] * inv, o[i][1] * inv, o[i][2] * inv, o[i][3] * inv);
        float4 w1 = make_float4(o[i][4] * inv, o[i][5] * inv, o[i][6] * inv, o[i][7] * inv);
        *(float4*)yp       = w0;
        *(float4*)(yp + 4) = w1;
    }
}

// ---------------------------------------------------------------------------
// kernel_launch: 6 kernel launches, graph-capturable, allocation-free.
// Input order (metadata): x_a, x_b, cos, sin, mask_a, Wqkv_a, Wqkv_b, Wproj_a, Wproj_b
// mask_a is deterministic (t even -> A) so it is not read.
// Output: y_a (2048x2048) followed by y_b (2048x2048), float32.
// ---------------------------------------------------------------------------
extern "C" void kernel_launch(void* const* d_in, const int* in_sizes, int n_in,
                              void* d_out, int out_size)
{
    (void)in_sizes; (void)n_in; (void)out_size;
    const float* x_a     = (const float*)d_in[0];
    const float* x_b     = (const float*)d_in[1];
    const float* cosp    = (const float*)d_in[2];
    const float* sinp    = (const float*)d_in[3];
    const float* Wqkv_a  = (const float*)d_in[5];
    const float* Wqkv_b  = (const float*)d_in[6];
    const float* Wproj_a = (const float*)d_in[7];
    const float* Wproj_b = (const float*)d_in[8];
    float* out = (float*)d_out;

    cudaFuncSetAttribute(flash_kernel,
                         cudaFuncAttributeMaxDynamicSharedMemorySize, FLASH_SMEM);

    // QKV projections: (2048 x 6144) = x @ Wqkv, scattered rows into g_qkv
    sgemm_map_kernel<<<dim3(48, 16), 256>>>(x_a, Wqkv_a, nullptr,
                                            E, E, C3, C3, /*parity=*/0, /*mapA=*/0, /*mapC=*/1);
    sgemm_map_kernel<<<dim3(48, 16), 256>>>(x_b, Wqkv_b, nullptr,
                                            E, E, C3, C3, 1, 0, 1);

    // RoPE on Q and K in-place
    rope_kernel<<<32768, 256>>>(cosp, sinp);

    // Causal flash attention -> g_y
    flash_kernel<<<dim3(32, 32), 256, FLASH_SMEM>>>();

    // Output projections: gather even/odd token rows of g_y
    sgemm_map_kernel<<<dim3(16, 16), 256>>>(nullptr, Wproj_a, out,
                                            E, E, E, E, 0, /*mapA=*/1, /*mapC=*/0);
    sgemm_map_kernel<<<dim3(16, 16), 256>>>(nullptr, Wproj_b, out + (size_t)2048 * 2048,
                                            E, E, E, E, 1, 1, 0);
}

// round 17
// speedup vs baseline: 1.8356x; 1.8353x over previous
#include <cuda_runtime.h>

// ---------------------------------------------------------------------------
// Problem constants (fixed by the reference)
// ---------------------------------------------------------------------------
#define T_TOT   2048            // tokens per batch
#define TA      1024            // tokens per stream per batch
#define E       2048            // embed dim (E_A == E_B == E_ATT)
#define C3      6144            // 3 * E_ATT
#define NH      16
#define HSZ     128
#define NTOK    4096            // B * T

// Scratch (allocation-free rule: device globals)
__device__ float g_qkv[(size_t)NTOK * C3];   // (B*T, 3*E) interleaved qkv
__device__ float g_y  [(size_t)NTOK * E];    // (B*T, E) attention output

// token row map: stream-local row r (b*1024 + ta)  ->  global token (b*2048 + 2*ta + parity)
__device__ __forceinline__ int map_row(int r, int parity) {
    return ((r >> 10) << 11) | ((r & 1023) << 1) | parity;
}

// fp32 -> tf32 (round-to-nearest-A), result is an fp32 bit pattern w/ low bits 0
__device__ __forceinline__ float f2tf(float f) {
    unsigned u;
    asm("cvt.rna.tf32.f32 %0, %1;" : "=r"(u) : "f"(f));
    return __uint_as_float(u);
}

__device__ __forceinline__ void mma_tf32(float* c, const unsigned* a, const unsigned* b) {
    asm volatile(
        "mma.sync.aligned.m16n8k8.row.col.f32.tf32.tf32.f32 "
        "{%0,%1,%2,%3}, {%4,%5,%6,%7}, {%8,%9}, {%0,%1,%2,%3};"
        : "+f"(c[0]), "+f"(c[1]), "+f"(c[2]), "+f"(c[3])
        : "r"(a[0]), "r"(a[1]), "r"(a[2]), "r"(a[3]), "r"(b[0]), "r"(b[1]));
}

// ---------------------------------------------------------------------------
// tf32 tensor-core GEMM: C[M,N] = A[M,K] @ B[K,N]
// 128x128x32 CTA tile, 256 thr = 8 warps, warp tile 64x32 (4x4 m16n8k8 tiles).
// mapA: gather A rows from g_y via map_row. mapC: scatter C rows into g_qkv.
// All dims multiples of tile sizes. fp32 accumulate.
// SMEM strides: As stride 36 (bank = 4*gID+tig, conflict-free),
//               Bs stride 136 (bank = 8*tig+gID, conflict-free).
// ---------------------------------------------------------------------------
#define AS_STRIDE 36
#define BS_STRIDE 136

__global__ __launch_bounds__(256, 2)
void mma_gemm_kernel(const float* __restrict__ A, const float* __restrict__ Bm,
                     float* __restrict__ C, int K, int lda, int ldb, int ldc,
                     int parity, int mapA, int mapC)
{
    __shared__ float As[128 * AS_STRIDE];   // [m][k]
    __shared__ float Bs[32 * BS_STRIDE];    // [k][n]

    const float* Abase = mapA ? g_y   : A;
    float*       Cbase = mapC ? g_qkv : C;

    const int tid  = threadIdx.x;
    const int m0   = blockIdx.y << 7;
    const int n0   = blockIdx.x << 7;
    const int wid  = tid >> 5;
    const int lane = tid & 31;
    const int wm   = (wid >> 2) << 6;    // 0 or 64
    const int wn   = (wid & 3) << 5;     // 0,32,64,96
    const int gID  = lane >> 2;          // 0..7
    const int tig  = lane & 3;           // 0..3

    float acc[4][4][4];
#pragma unroll
    for (int mt = 0; mt < 4; ++mt)
#pragma unroll
        for (int nt = 0; nt < 4; ++nt)
#pragma unroll
            for (int i = 0; i < 4; ++i) acc[mt][nt][i] = 0.f;

    // Global load mapping.
    // A: float4 idx = tid + 256*i -> row = (tid>>3)+32*i, col4 = (tid&7)*4
    // B: float4 idx = tid + 256*i -> k   = (tid>>5)+8*i,  n4   = (tid&31)*4
    const int acol = (tid & 7) << 2;
    const int asr  = tid >> 3;                 // smem row base for A stores
    const float* Ap[4];
#pragma unroll
    for (int i = 0; i < 4; ++i) {
        int r = m0 + asr + 32 * i;
        if (mapA) r = map_row(r, parity);
        Ap[i] = Abase + (size_t)r * lda + acol;
    }
    const int bkr  = tid >> 5;                 // 0..7
    const int bcol = (tid & 31) << 2;
    const float* Bp = Bm + (size_t)bkr * ldb + n0 + bcol;

    for (int kt = 0; kt < K; kt += 32) {
#pragma unroll
        for (int i = 0; i < 4; ++i) {
            float4 v = *(const float4*)(Ap[i] + kt);
            float* d = &As[(asr + 32 * i) * AS_STRIDE + acol];
            d[0] = f2tf(v.x); d[1] = f2tf(v.y); d[2] = f2tf(v.z); d[3] = f2tf(v.w);
        }
#pragma unroll
        for (int i = 0; i < 4; ++i) {
            float4 v = *(const float4*)(Bp + (size_t)(kt + 8 * i) * ldb);
            float* d = &Bs[(bkr + 8 * i) * BS_STRIDE + bcol];
            d[0] = f2tf(v.x); d[1] = f2tf(v.y); d[2] = f2tf(v.z); d[3] = f2tf(v.w);
        }
        __syncthreads();

#pragma unroll
        for (int k8 = 0; k8 < 32; k8 += 8) {
            unsigned a[4][4], b[4][2];
#pragma unroll
            for (int mt = 0; mt < 4; ++mt) {
                const float* ap = &As[(wm + mt * 16 + gID) * AS_STRIDE + k8 + tig];
                a[mt][0] = __float_as_uint(ap[0]);
                a[mt][1] = __float_as_uint(ap[8 * AS_STRIDE]);
                a[mt][2] = __float_as_uint(ap[4]);
                a[mt][3] = __float_as_uint(ap[8 * AS_STRIDE + 4]);
            }
#pragma unroll
            for (int nt = 0; nt < 4; ++nt) {
                const float* bp = &Bs[(k8 + tig) * BS_STRIDE + wn + nt * 8 + gID];
                b[nt][0] = __float_as_uint(bp[0]);
                b[nt][1] = __float_as_uint(bp[4 * BS_STRIDE]);
            }
#pragma unroll
            for (int mt = 0; mt < 4; ++mt)
#pragma unroll
                for (int nt = 0; nt < 4; ++nt)
                    mma_tf32(acc[mt][nt], a[mt], b[nt]);
        }
        __syncthreads();
    }

    // Epilogue: c0,c1 -> (row, 2*tig..+1), c2,c3 -> (row+8, same cols)
#pragma unroll
    for (int mt = 0; mt < 4; ++mt) {
        int r0 = m0 + wm + mt * 16 + gID;
        int r1 = r0 + 8;
        int g0 = mapC ? map_row(r0, parity) : r0;
        int g1 = mapC ? map_row(r1, parity) : r1;
        float* c0p = Cbase + (size_t)g0 * ldc + n0 + wn + (tig << 1);
        float* c1p = Cbase + (size_t)g1 * ldc + n0 + wn + (tig << 1);
#pragma unroll
        for (int nt = 0; nt < 4; ++nt) {
            *(float2*)(c0p + nt * 8) = make_float2(acc[mt][nt][0], acc[mt][nt][1]);
            *(float2*)(c1p + nt * 8) = make_float2(acc[mt][nt][2], acc[mt][nt][3]);
        }
    }
}

// ---------------------------------------------------------------------------
// RoPE in-place on Q and K sections of g_qkv.
// ---------------------------------------------------------------------------
__global__ void rope_kernel(const float* __restrict__ cp, const float* __restrict__ sp)
{
    int idx = blockIdx.x * blockDim.x + threadIdx.x;   // 0 .. 8388607
    int d   = idx & 63;
    int h   = (idx >> 6) & 15;
    int qk  = (idx >> 10) & 1;
    int tok = idx >> 11;                 // 0..4095
    int t   = tok & (T_TOT - 1);
    size_t base = (size_t)tok * C3 + (qk << 11) + (h << 7);
    float x1 = g_qkv[base + d];
    float x2 = g_qkv[base + d + 64];
    float c1 = cp[(t << 7) + d],      s1 = sp[(t << 7) + d];
    float c2 = cp[(t << 7) + d + 64], s2 = sp[(t << 7) + d + 64];
    g_qkv[base + d]      = x1 * c1 - x2 * s1;
    g_qkv[base + d + 64] = x2 * c2 + x1 * s2;
}

// ---------------------------------------------------------------------------
// Causal flash attention, fp32. BQ = BK = 64, D = 128, 256 threads.
// ---------------------------------------------------------------------------
#define FLASH_SMEM ((128 * 65 * 2 + 64 * 128 + 64 * 65) * 4)

__global__ __launch_bounds__(256, 1)
void flash_kernel()
{
    extern __shared__ float sm[];
    float* sQ = sm;                       // [128][65]  k-major (transposed)
    float* sK = sm + 128 * 65;            // [128][65]  k-major (transposed)
    float* sV = sK + 128 * 65;            // [64][128]  natural
    float* sP = sV + 64 * 128;            // [64][65]

    const int tid   = threadIdx.x;
    const int qtile = 31 - blockIdx.x;    // heavy (late) q-tiles scheduled first
    const int bh    = blockIdx.y;
    const int b     = bh >> 4;
    const int h     = bh & 15;
    const int qt0   = qtile << 6;
    const int rm    = tid >> 4;
    const int cn    = tid & 15;

    const float* base = g_qkv + (size_t)b * T_TOT * C3 + (h << 7);

    // Load Q tile, transposed into sQ[k][r]
    for (int idx = tid; idx < 2048; idx += 256) {
        int r = idx >> 5, d4 = (idx & 31) << 2;
        float4 v = *(const float4*)(base + (size_t)(qt0 + r) * C3 + d4);
        sQ[(d4 + 0) * 65 + r] = v.x;
        sQ[(d4 + 1) * 65 + r] = v.y;
        sQ[(d4 + 2) * 65 + r] = v.z;
        sQ[(d4 + 3) * 65 + r] = v.w;
    }

    float o[4][8];
#pragma unroll
    for (int i = 0; i < 4; ++i)
#pragma unroll
        for (int j = 0; j < 8; ++j) o[i][j] = 0.f;
    float mrow[4] = {-1e30f, -1e30f, -1e30f, -1e30f};
    float lrow[4] = {0.f, 0.f, 0.f, 0.f};
    const float scale = 0.08838834764831845f;   // 1/sqrt(128)

    for (int kt = 0; kt <= qtile; ++kt) {
        const int kt0 = kt << 6;
        __syncthreads();   // previous iteration done with sK/sV/sP
        for (int idx = tid; idx < 2048; idx += 256) {
            int r = idx >> 5, d4 = (idx & 31) << 2;
            const float* rp = base + (size_t)(kt0 + r) * C3 + d4;
            float4 kv = *(const float4*)(rp + 2048);
            sK[(d4 + 0) * 65 + r] = kv.x;
            sK[(d4 + 1) * 65 + r] = kv.y;
            sK[(d4 + 2) * 65 + r] = kv.z;
            sK[(d4 + 3) * 65 + r] = kv.w;
            float4 vv = *(const float4*)(rp + 4096);
            *(float4*)&sV[(r << 7) + d4] = vv;
        }
        __syncthreads();

        float acc[4][4];
#pragma unroll
        for (int i = 0; i < 4; ++i)
#pragma unroll
            for (int j = 0; j < 4; ++j) acc[i][j] = 0.f;

#pragma unroll 4
        for (int k = 0; k < 128; ++k) {
            const float* qr = sQ + k * 65 + (rm << 2);
            const float* kr = sK + k * 65 + (cn << 2);
            float a0 = qr[0], a1 = qr[1], a2 = qr[2], a3 = qr[3];
            float b0 = kr[0], b1 = kr[1], b2 = kr[2], b3 = kr[3];
            acc[0][0] += a0 * b0; acc[0][1] += a0 * b1; acc[0][2] += a0 * b2; acc[0][3] += a0 * b3;
            acc[1][0] += a1 * b0; acc[1][1] += a1 * b1; acc[1][2] += a1 * b2; acc[1][3] += a1 * b3;
            acc[2][0] += a2 * b0; acc[2][1] += a2 * b1; acc[2][2] += a2 * b2; acc[2][3] += a2 * b3;
            acc[3][0] += a3 * b0; acc[3][1] += a3 * b1; acc[3][2] += a3 * b2; acc[3][3] += a3 * b3;
        }

        const bool diag = (kt == qtile);
#pragma unroll
        for (int i = 0; i < 4; ++i) {
            float s0 = acc[i][0] * scale, s1 = acc[i][1] * scale;
            float s2 = acc[i][2] * scale, s3 = acc[i][3] * scale;
            if (diag) {
                int iq = (rm << 2) + i;
                int jc = cn << 2;
                if (jc + 0 > iq) s0 = -1e30f;
                if (jc + 1 > iq) s1 = -1e30f;
                if (jc + 2 > iq) s2 = -1e30f;
                if (jc + 3 > iq) s3 = -1e30f;
            }
            float mx = fmaxf(fmaxf(s0, s1), fmaxf(s2, s3));
            mx = fmaxf(mx, __shfl_xor_sync(0xffffffffu, mx, 1));
            mx = fmaxf(mx, __shfl_xor_sync(0xffffffffu, mx, 2));
            mx = fmaxf(mx, __shfl_xor_sync(0xffffffffu, mx, 4));
            mx = fmaxf(mx, __shfl_xor_sync(0xffffffffu, mx, 8));
            float mnew = fmaxf(mrow[i], mx);
            float corr = __expf(mrow[i] - mnew);
            float p0 = __expf(s0 - mnew);
            float p1 = __expf(s1 - mnew);
            float p2 = __expf(s2 - mnew);
            float p3 = __expf(s3 - mnew);
            float ls = (p0 + p1) + (p2 + p3);
            ls += __shfl_xor_sync(0xffffffffu, ls, 1);
            ls += __shfl_xor_sync(0xffffffffu, ls, 2);
            ls += __shfl_xor_sync(0xffffffffu, ls, 4);
            ls += __shfl_xor_sync(0xffffffffu, ls, 8);
            lrow[i] = lrow[i] * corr + ls;
            mrow[i] = mnew;
#pragma unroll
            for (int j = 0; j < 8; ++j) o[i][j] *= corr;
            float* pr = sP + ((rm << 2) + i) * 65 + (cn << 2);
            pr[0] = p0; pr[1] = p1; pr[2] = p2; pr[3] = p3;
        }
        __syncthreads();   // sP visible to all

#pragma unroll 2
        for (int j = 0; j < 64; ++j) {
            float p0 = sP[((rm << 2) + 0) * 65 + j];
            float p1 = sP[((rm << 2) + 1) * 65 + j];
            float p2 = sP[((rm << 2) + 2) * 65 + j];
            float p3 = sP[((rm << 2) + 3) * 65 + j];
            float4 v0 = *(const float4*)&sV[(j << 7) + (cn << 3)];
            float4 v1 = *(const float4*)&sV[(j << 7) + (cn << 3) + 4];
            o[0][0] += p0 * v0.x; o[0][1] += p0 * v0.y; o[0][2] += p0 * v0.z; o[0][3] += p0 * v0.w;
            o[0][4] += p0 * v1.x; o[0][5] += p0 * v1.y; o[0][6] += p0 * v1.z; o[0][7] += p0 * v1.w;
            o[1][0] += p1 * v0.x; o[1][1] += p1 * v0.y; o[1][2] += p1 * v0.z; o[1][3] += p1 * v0.w;
            o[1][4] += p1 * v1.x; o[1][5] += p1 * v1.y; o[1][6] += p1 * v1.z; o[1][7] += p1 * v1.w;
            o[2][0] += p2 * v0.x; o[2][1] += p2 * v0.y; o[2][2] += p2 * v0.z; o[2][3] += p2 * v0.w;
            o[2][4] += p2 * v1.x; o[2][5] += p2 * v1.y; o[2][6] += p2 * v1.z; o[2][7] += p2 * v1.w;
            o[3][0] += p3 * v0.x; o[3][1] += p3 * v0.y; o[3][2] += p3 * v0.z; o[3][3] += p3 * v0.w;
            o[3][4] += p3 * v1.x; o[3][5] += p3 * v1.y; o[3][6] += p3 * v1.z; o[3][7] += p3 * v1.w;
        }
    }

#pragma unroll
    for (int i = 0; i < 4; ++i) {
        float inv = 1.f / lrow[i];
        int t = qt0 + (rm << 2) + i;
        float* yp = g_y + ((size_t)b * T_TOT + t) * E + (h << 7) + (cn << 3);
        float4 w0 = make_float4(o[i][0] * inv, o[i][1] * inv, o[i][2] * inv, o[i][3] * inv);
        float4 w1 = make_float4(o[i][4] * inv, o[i][5] * inv, o[i][6] * inv, o[i][7] * inv);
        *(float4*)yp       = w0;
        *(float4*)(yp + 4) = w1;
    }
}

// ---------------------------------------------------------------------------
// kernel_launch: 6 kernel launches, graph-capturable, allocation-free.
// Input order: x_a, x_b, cos, sin, mask_a, Wqkv_a, Wqkv_b, Wproj_a, Wproj_b
// Output: y_a (2048x2048) followed by y_b (2048x2048), float32.
// ---------------------------------------------------------------------------
extern "C" void kernel_launch(void* const* d_in, const int* in_sizes, int n_in,
                              void* d_out, int out_size)
{
    (void)in_sizes; (void)n_in; (void)out_size;
    const float* x_a     = (const float*)d_in[0];
    const float* x_b     = (const float*)d_in[1];
    const float* cosp    = (const float*)d_in[2];
    const float* sinp    = (const float*)d_in[3];
    const float* Wqkv_a  = (const float*)d_in[5];
    const float* Wqkv_b  = (const float*)d_in[6];
    const float* Wproj_a = (const float*)d_in[7];
    const float* Wproj_b = (const float*)d_in[8];
    float* out = (float*)d_out;

    cudaFuncSetAttribute(flash_kernel,
                         cudaFuncAttributeMaxDynamicSharedMemorySize, FLASH_SMEM);

    // QKV projections: (2048 x 6144) = x @ Wqkv, scattered rows into g_qkv
    mma_gemm_kernel<<<dim3(48, 16), 256>>>(x_a, Wqkv_a, nullptr,
                                           E, E, C3, C3, /*parity=*/0, /*mapA=*/0, /*mapC=*/1);
    mma_gemm_kernel<<<dim3(48, 16), 256>>>(x_b, Wqkv_b, nullptr,
                                           E, E, C3, C3, 1, 0, 1);

    // RoPE on Q and K in-place
    rope_kernel<<<32768, 256>>>(cosp, sinp);

    // Causal flash attention -> g_y
    flash_kernel<<<dim3(32, 32), 256, FLASH_SMEM>>>();

    // Output projections: gather even/odd token rows of g_y
    mma_gemm_kernel<<<dim3(16, 16), 256>>>(nullptr, Wproj_a, out,
                                           E, E, E, E, 0, /*mapA=*/1, /*mapC=*/0);
    mma_gemm_kernel<<<dim3(16, 16), 256>>>(nullptr, Wproj_b, out + (size_t)2048 * 2048,
                                           E, E, E, E, 1, 1, 0);
}